// round 6
// baseline (speedup 1.0000x reference)
#include <cuda_runtime.h>
#include <cuda_fp16.h>
#include <math.h>
#include <stdint.h>

#define DIM   1152
#define HEADS 16
#define HD    72
#define HDE   73
#define HID   4608
#define HID2  9216
#define BB    2
#define NN    4096
#define MM    (BB*NN)        // 8192
#define TEMB6 (6*DIM)

// ---------------- scratch (device globals; no allocation) ----------------
__device__ __half g_xh[MM*DIM];
__device__ float  g_q[MM*DIM];
__device__ float  g_k[MM*DIM];
__device__ float  g_v[MM*DIM];
__device__ __half g_attnh[MM*DIM];
__device__ float  g_h2[MM*DIM];
__device__ __half g_yh[(size_t)MM*HID2];
__device__ __half g_zh[(size_t)MM*HID];
__device__ float  g_kvp[8*BB*HEADS*HD*HDE];
__device__ float  g_kv[BB*HEADS*HD*HDE];
__device__ __half g_wq[DIM*DIM];
__device__ __half g_wk[DIM*DIM];
__device__ __half g_wv[DIM*DIM];
__device__ __half g_wo[DIM*DIM];
__device__ __half g_winv[2*HID*DIM];
__device__ __half g_wpt[DIM*HID];

// ---------------- helpers ----------------
__device__ __forceinline__ uint32_t smem_u32(const void* p) {
    uint32_t a;
    asm("{ .reg .u64 t; cvta.to.shared.u64 t, %1; cvt.u32.u64 %0, t; }"
        : "=r"(a) : "l"(p));
    return a;
}
#define SWZ128(off) ((off) ^ (((off) >> 3) & 0x70))
#define CPA16(dst_u32, src_ptr) \
    asm volatile("cp.async.cg.shared.global [%0], [%1], 16;" \
        :: "r"(dst_u32), "l"(src_ptr))
#define LDSM4(r0, r1, r2, r3, addr) \
    asm volatile("ldmatrix.sync.aligned.m8n8.x4.shared.b16 {%0,%1,%2,%3}, [%4];" \
        : "=r"(r0), "=r"(r1), "=r"(r2), "=r"(r3) : "r"(addr))

__device__ __forceinline__ void mma_f16(float c[4], const unsigned a0, const unsigned a1,
                                        const unsigned a2, const unsigned a3,
                                        const unsigned b0, const unsigned b1) {
    asm volatile(
        "mma.sync.aligned.m16n8k16.row.col.f32.f16.f16.f32 "
        "{%0,%1,%2,%3}, {%4,%5,%6,%7}, {%8,%9}, {%0,%1,%2,%3};\n"
        : "+f"(c[0]), "+f"(c[1]), "+f"(c[2]), "+f"(c[3])
        : "r"(a0), "r"(a1), "r"(a2), "r"(a3), "r"(b0), "r"(b1));
}

// ---------------- fp32 -> half weight conversion ----------------
__global__ void cvt_half_kernel(const float4* __restrict__ src,
                                __half* __restrict__ dst, int n4)
{
    int i = blockIdx.x * 256 + threadIdx.x;
    if (i < n4) {
        float4 v = src[i];
        __half2 lo = __floats2half2_rn(v.x, v.y);
        __half2 hi = __floats2half2_rn(v.z, v.w);
        *(uint2*)(dst + (size_t)i*4) = make_uint2(*(unsigned*)&lo, *(unsigned*)&hi);
    }
}

// ---------------- adaLN modulation + RMSNorm -> half ----------------
__global__ void __launch_bounds__(288) modrms_kernel(
    const float* __restrict__ in, const float* __restrict__ temb,
    const float* __restrict__ sst, __half* __restrict__ out, int idx0)
{
    int row = blockIdx.x;
    int b   = row >> 12;
    const float* ip = in + (size_t)row*DIM;
    int d = threadIdx.x * 4;
    float4 h = *(const float4*)(ip + d);
    float ss = h.x*h.x + h.y*h.y + h.z*h.z + h.w*h.w;
    #pragma unroll
    for (int o = 16; o > 0; o >>= 1) ss += __shfl_down_sync(0xffffffffu, ss, o);
    __shared__ float red[9];
    int lane = threadIdx.x & 31, wid = threadIdx.x >> 5;
    if (lane == 0) red[wid] = ss;
    __syncthreads();
    if (threadIdx.x == 0) {
        float t = 0.f;
        #pragma unroll
        for (int i = 0; i < 9; i++) t += red[i];
        red[0] = rsqrtf(t * (1.0f/DIM) + 1e-6f);
    }
    __syncthreads();
    float r = red[0];
    const float* tb = temb + b*TEMB6;
    float4 sh, sc;
    {
        const float* s0 = sst + idx0*DIM + d;
        const float* t0 = tb  + idx0*DIM + d;
        const float* s1 = sst + (idx0+1)*DIM + d;
        const float* t1 = tb  + (idx0+1)*DIM + d;
        sh = make_float4(s0[0]+t0[0], s0[1]+t0[1], s0[2]+t0[2], s0[3]+t0[3]);
        sc = make_float4(s1[0]+t1[0], s1[1]+t1[1], s1[2]+t1[2], s1[3]+t1[3]);
    }
    __half2 o0 = __floats2half2_rn(h.x*r*(1.f+sc.x) + sh.x, h.y*r*(1.f+sc.y) + sh.y);
    __half2 o1 = __floats2half2_rn(h.z*r*(1.f+sc.z) + sh.z, h.w*r*(1.f+sc.w) + sh.w);
    *(uint2*)(out + (size_t)row*DIM + d) = make_uint2(*(unsigned*)&o0, *(unsigned*)&o1);
}

// ---------------- fp16 mma.sync NT GEMM, ldmatrix + SW128, 3-stage ----------
// C[M,Ntot] = A[M,K](half) * Bw[Ntot,K](half)^T, fp32 accum
// EPI: 0 relu(acc+bias)->f32, 1 acc+bias->f32, 2 gate*(acc+bias)+extra->f32,
//      3 silu(acc+bias)->half, 4 extra + gate*acc->f32
#define BM 128
#define BN 128
#define BK 64             // halves per row = 128 bytes (SW128 atom)
#define NSTG 3
#define TILEA (BM*BK*2)   // 16384 bytes
#define TILEB (BN*BK*2)   // 16384 bytes
#define STGB  (TILEA + TILEB)              // 32768
#define GEMM_SMEM (NSTG*STGB)              // 98304

template<int EPI, typename OutT>
__global__ void __launch_bounds__(256, 2) gemm_f16(
    const __half* __restrict__ A, const __half* __restrict__ Bw,
    const float* __restrict__ bias, OutT* __restrict__ C,
    int K, int Ntot,
    const float* __restrict__ extra,
    const float* __restrict__ temb, const float* __restrict__ sst, int gidx)
{
    extern __shared__ char smem[];
    const uint32_t sbase = smem_u32(smem);
    const int tid = threadIdx.x;
    const int lane = tid & 31, warp = tid >> 5;
    const int wm = warp >> 2, wn = warp & 3;      // 2x4 warps -> 64x32 per warp
    const int m0 = blockIdx.y * BM, n0 = blockIdx.x * BN;
    const int KT = K / BK;

    // loader mapping: thread t -> row t>>1 (0..127), 4 chunks of 16B
    const int lrow = tid >> 1;
    const int lch0 = (tid & 1) * 4;
    const uint32_t lxor = (uint32_t)((lrow & 7) << 4);
    const __half* Ap = A  + (size_t)(m0 + lrow) * K + lch0*8;
    const __half* Bp = Bw + (size_t)(n0 + lrow) * K + lch0*8;

    #define LOAD_STAGE(t) do {                                              \
        uint32_t st_ = sbase + ((t) % NSTG) * STGB;                         \
        uint32_t sa_ = st_ + lrow*128;                                      \
        uint32_t sb_ = st_ + TILEA + lrow*128;                              \
        const __half* Ap_ = Ap + (size_t)(t) * BK;                          \
        const __half* Bp_ = Bp + (size_t)(t) * BK;                          \
        _Pragma("unroll")                                                   \
        for (int c_ = 0; c_ < 4; c_++) {                                    \
            uint32_t co_ = (uint32_t)((lch0 + c_) * 16) ^ lxor;             \
            CPA16(sa_ + co_, Ap_ + c_*8);                                   \
            CPA16(sb_ + co_, Bp_ + c_*8);                                   \
        }                                                                   \
        asm volatile("cp.async.commit_group;");                             \
    } while (0)

    float acc[4][4][4];
    #pragma unroll
    for (int i = 0; i < 4; i++)
        #pragma unroll
        for (int j = 0; j < 4; j++)
            #pragma unroll
            for (int q = 0; q < 4; q++) acc[i][j][q] = 0.f;

    LOAD_STAGE(0);
    LOAD_STAGE(1);

    // fragment addressing (per-lane constants)
    const int frow = lane & 15;           // row within 16-row group
    const uint32_t fseg = (uint32_t)((lane >> 4) * 16);
    uint32_t a_base[4], a_xor[4], b_base[2], b_xor[2];
    #pragma unroll
    for (int mt = 0; mt < 4; mt++) {
        int r = wm*64 + mt*16 + frow;
        a_base[mt] = (uint32_t)(r * 128);
        a_xor[mt]  = (uint32_t)((r & 7) << 4);
    }
    #pragma unroll
    for (int g = 0; g < 2; g++) {
        int r = wn*32 + g*16 + frow;
        b_base[g] = (uint32_t)(TILEA + r * 128);
        b_xor[g]  = (uint32_t)((r & 7) << 4);
    }

    for (int kt = 0; kt < KT; kt++) {
        if (kt + 2 < KT) LOAD_STAGE(kt + 2);
        int newer = KT - 1 - kt;
        if (newer >= 2)      asm volatile("cp.async.wait_group 2;");
        else if (newer == 1) asm volatile("cp.async.wait_group 1;");
        else                 asm volatile("cp.async.wait_group 0;");
        __syncthreads();

        uint32_t stg = sbase + (kt % NSTG) * STGB;
        #pragma unroll
        for (int ks = 0; ks < 4; ks++) {
            uint32_t colk = (uint32_t)(ks * 32) + fseg;
            unsigned a[4][4], bb[2][4];
            #pragma unroll
            for (int mt = 0; mt < 4; mt++)
                LDSM4(a[mt][0], a[mt][1], a[mt][2], a[mt][3],
                      stg + a_base[mt] + (colk ^ a_xor[mt]));
            #pragma unroll
            for (int g = 0; g < 2; g++)
                LDSM4(bb[g][0], bb[g][1], bb[g][2], bb[g][3],
                      stg + b_base[g] + (colk ^ b_xor[g]));
            #pragma unroll
            for (int mt = 0; mt < 4; mt++) {
                #pragma unroll
                for (int nt = 0; nt < 4; nt++) {
                    int g = nt >> 1, s = nt & 1;
                    mma_f16(acc[mt][nt], a[mt][0], a[mt][1], a[mt][2], a[mt][3],
                            bb[g][s], bb[g][s + 2]);
                }
            }
        }
        __syncthreads();
    }

    // epilogue (fragment layout: rr=lane>>2, cc=lane&3)
    const int rr = lane >> 2, cc = lane & 3;
    #pragma unroll
    for (int mt = 0; mt < 4; mt++) {
        #pragma unroll
        for (int half_ = 0; half_ < 2; half_++) {
            int m = m0 + wm*64 + mt*16 + rr + half_*8;
            int bidx = m >> 12;
            #pragma unroll
            for (int nt = 0; nt < 4; nt++) {
                int n = n0 + wn*32 + nt*8 + cc*2;
                float v0 = acc[mt][nt][half_*2+0];
                float v1 = acc[mt][nt][half_*2+1];
                if (EPI == 0) {
                    v0 += bias[n];   v0 = v0 > 0.f ? v0 : 0.f;
                    v1 += bias[n+1]; v1 = v1 > 0.f ? v1 : 0.f;
                } else if (EPI == 1) {
                    v0 += bias[n]; v1 += bias[n+1];
                } else if (EPI == 2) {
                    v0 += bias[n]; v1 += bias[n+1];
                    float g0 = sst[gidx*DIM + n]   + temb[bidx*TEMB6 + gidx*DIM + n];
                    float g1 = sst[gidx*DIM + n+1] + temb[bidx*TEMB6 + gidx*DIM + n+1];
                    v0 = g0 * v0 + extra[(size_t)m*DIM + n];
                    v1 = g1 * v1 + extra[(size_t)m*DIM + n+1];
                } else if (EPI == 3) {
                    v0 += bias[n];   v0 = v0 / (1.f + expf(-v0));
                    v1 += bias[n+1]; v1 = v1 / (1.f + expf(-v1));
                } else if (EPI == 4) {
                    float g0 = sst[gidx*DIM + n]   + temb[bidx*TEMB6 + gidx*DIM + n];
                    float g1 = sst[gidx*DIM + n+1] + temb[bidx*TEMB6 + gidx*DIM + n+1];
                    v0 = extra[(size_t)m*DIM + n]   + g0 * v0;
                    v1 = extra[(size_t)m*DIM + n+1] + g1 * v1;
                }
                if (sizeof(OutT) == 4) {
                    *(float2*)((float*)C + (size_t)m*Ntot + n) = make_float2(v0, v1);
                } else {
                    __half2 hv = __floats2half2_rn(v0, v1);
                    *(unsigned*)((__half*)C + (size_t)m*Ntot + n) = *(unsigned*)&hv;
                }
            }
        }
    }
}

// ---------------- kv = sum_n k (x) [v,1]  (split over 8 N-chunks) -----------
__global__ void __launch_bounds__(264) kv_kernel(
    const float* __restrict__ Kq, const float* __restrict__ Vq)
{
    int bh = blockIdx.x;
    int b = bh >> 4, h = bh & 15;
    int chunk = blockIdx.y;
    __shared__ float ks[8][72];
    __shared__ float vs[8][80];
    int tid = threadIdx.x;
    if (tid < 8*7) vs[tid/7][73 + tid%7] = 0.f;
    int d0 = (tid % 24) * 3;
    int e0 = (tid / 24) * 7;
    float acc[3][7];
    #pragma unroll
    for (int i = 0; i < 3; i++)
        #pragma unroll
        for (int j = 0; j < 7; j++) acc[i][j] = 0.f;

    const float* kbase = Kq + (size_t)(b*NN)*DIM + h*HD;
    const float* vbase = Vq + (size_t)(b*NN)*DIM + h*HD;
    int nstart = chunk * 512;

    for (int nn = 0; nn < 512; nn += 8) {
        __syncthreads();
        for (int i = tid; i < 8*72; i += 264) {
            int r = i / 72, d = i - r*72;
            ks[r][d] = kbase[(size_t)(nstart+nn+r)*DIM + d];
        }
        for (int i = tid; i < 8*73; i += 264) {
            int r = i / 73, e = i - r*73;
            vs[r][e] = (e < 72) ? vbase[(size_t)(nstart+nn+r)*DIM + e] : 1.0f;
        }
        __syncthreads();
        #pragma unroll
        for (int r = 0; r < 8; r++) {
            float kk[3], vv[7];
            #pragma unroll
            for (int i = 0; i < 3; i++) kk[i] = ks[r][d0+i];
            #pragma unroll
            for (int j = 0; j < 7; j++) vv[j] = vs[r][e0+j];
            #pragma unroll
            for (int i = 0; i < 3; i++)
                #pragma unroll
                for (int j = 0; j < 7; j++) acc[i][j] += kk[i]*vv[j];
        }
    }
    float* outp = g_kvp + ((size_t)chunk * 32 + bh) * (HD*HDE);
    #pragma unroll
    for (int i = 0; i < 3; i++)
        #pragma unroll
        for (int j = 0; j < 7; j++) {
            int e = e0 + j;
            if (e < HDE) outp[(d0+i)*HDE + e] = acc[i][j];
        }
}

__global__ void kv_reduce_kernel()
{
    int j = blockIdx.x * 256 + threadIdx.x;
    const int TOT = BB*HEADS*HD*HDE;
    if (j >= TOT) return;
    float s = 0.f;
    #pragma unroll
    for (int c = 0; c < 8; c++) s += g_kvp[(size_t)c*TOT + j];
    g_kv[j] = s;
}

// ---------------- out = (q . kv), numerator/denominator -> half -------------
__global__ void __launch_bounds__(320) attn_apply_kernel(
    const float* __restrict__ Q, __half* __restrict__ attn)
{
    int bh = blockIdx.x;
    int b = bh >> 4, h = bh & 15;
    int n0 = blockIdx.y * 64;
    __shared__ float kvs[72][80];
    __shared__ float qs[64][72];
    int tid = threadIdx.y * 80 + threadIdx.x;

    const float* kvsrc = g_kv + (size_t)bh * (HD*HDE);
    for (int i = tid; i < HD*HDE; i += 320) kvs[i/HDE][i%HDE] = kvsrc[i];
    const float* qbase = Q + (size_t)(b*NN + n0)*DIM + h*HD;
    for (int i = tid; i < 64*72; i += 320) {
        int r = i / 72, d = i - r*72;
        qs[r][d] = qbase[(size_t)r*DIM + d];
    }
    __syncthreads();

    int e = threadIdx.x, ty = threadIdx.y;
    float acc[16];
    #pragma unroll
    for (int r = 0; r < 16; r++) acc[r] = 0.f;
    if (e < HDE) {
        for (int d = 0; d < 72; d++) {
            float kvv = kvs[d][e];
            #pragma unroll
            for (int r = 0; r < 16; r++) acc[r] += qs[ty + r*4][d] * kvv;
        }
    }
    __syncthreads();
    float* outs = &kvs[0][0];
    if (e < HDE) {
        #pragma unroll
        for (int r = 0; r < 16; r++) outs[(ty + r*4)*80 + e] = acc[r];
    }
    __syncthreads();
    __half* ob = attn + (size_t)(b*NN + n0)*DIM + h*HD;
    for (int i = tid; i < 64*72; i += 320) {
        int r = i / 72, d = i - r*72;
        ob[(size_t)r*DIM + d] = __float2half_rn(
            outs[r*80 + d] / (outs[r*80 + 72] + 1e-15f));
    }
}

// ---------------- depthwise conv (k=3, pad 1) + GLU (half in/out) -----------
__global__ void dwglu_kernel(const __half* __restrict__ Y,
                             const float* __restrict__ Wdw,
                             const float* __restrict__ bdw,
                             __half* __restrict__ Z)
{
    int idx = blockIdx.x * 256 + threadIdx.x;
    const int TOT = BB*NN*HID;
    if (idx >= TOT) return;
    int c = idx % HID;
    int n = (idx / HID) & (NN-1);
    int b = idx / (HID*NN);

    float xg = bdw[c];
    float gt = bdw[c + HID];
    #pragma unroll
    for (int t = 0; t < 3; t++) {
        int nn = n + t - 1;
        if (nn >= 0 && nn < NN) {
            const __half* yr = Y + (size_t)(b*NN + nn) * HID2;
            xg += __half2float(yr[c])       * Wdw[c*3 + t];
            gt += __half2float(yr[c + HID]) * Wdw[(c + HID)*3 + t];
        }
    }
    float s = gt / (1.f + expf(-gt));
    Z[(size_t)idx] = __float2half_rn(xg * s);
}

// ---------------- host launcher ----------------
extern "C" void kernel_launch(void* const* d_in, const int* in_sizes, int n_in,
                              void* d_out, int out_size)
{
    const float* hidden = (const float*)d_in[0];
    const float* temb   = (const float*)d_in[1];
    const float* sst    = (const float*)d_in[2];
    const float* Wq     = (const float*)d_in[3];
    const float* bq     = (const float*)d_in[4];
    const float* Wk     = (const float*)d_in[5];
    const float* bk     = (const float*)d_in[6];
    const float* Wv     = (const float*)d_in[7];
    const float* bv     = (const float*)d_in[8];
    const float* Wo     = (const float*)d_in[9];
    const float* bo     = (const float*)d_in[10];
    const float* W_inv  = (const float*)d_in[11];
    const float* b_inv  = (const float*)d_in[12];
    const float* W_dw   = (const float*)d_in[13];
    const float* b_dw   = (const float*)d_in[14];
    const float* W_pt   = (const float*)d_in[15];
    float* out = (float*)d_out;

    __half *xh, *attnh, *yh, *zh, *wq, *wk, *wv, *wo, *winv, *wpt;
    float *q, *k, *v, *h2;
    cudaGetSymbolAddress((void**)&xh,    g_xh);
    cudaGetSymbolAddress((void**)&q,     g_q);
    cudaGetSymbolAddress((void**)&k,     g_k);
    cudaGetSymbolAddress((void**)&v,     g_v);
    cudaGetSymbolAddress((void**)&attnh, g_attnh);
    cudaGetSymbolAddress((void**)&h2,    g_h2);
    cudaGetSymbolAddress((void**)&yh,    g_yh);
    cudaGetSymbolAddress((void**)&zh,    g_zh);
    cudaGetSymbolAddress((void**)&wq,    g_wq);
    cudaGetSymbolAddress((void**)&wk,    g_wk);
    cudaGetSymbolAddress((void**)&wv,    g_wv);
    cudaGetSymbolAddress((void**)&wo,    g_wo);
    cudaGetSymbolAddress((void**)&winv,  g_winv);
    cudaGetSymbolAddress((void**)&wpt,   g_wpt);

    cudaFuncSetAttribute(gemm_f16<0,float>,  cudaFuncAttributeMaxDynamicSharedMemorySize, GEMM_SMEM);
    cudaFuncSetAttribute(gemm_f16<1,float>,  cudaFuncAttributeMaxDynamicSharedMemorySize, GEMM_SMEM);
    cudaFuncSetAttribute(gemm_f16<2,float>,  cudaFuncAttributeMaxDynamicSharedMemorySize, GEMM_SMEM);
    cudaFuncSetAttribute(gemm_f16<3,__half>, cudaFuncAttributeMaxDynamicSharedMemorySize, GEMM_SMEM);
    cudaFuncSetAttribute(gemm_f16<4,float>,  cudaFuncAttributeMaxDynamicSharedMemorySize, GEMM_SMEM);

    // 0) convert weights to half
    cvt_half_kernel<<<(DIM*DIM/4 + 255)/256, 256>>>((const float4*)Wq, wq, DIM*DIM/4);
    cvt_half_kernel<<<(DIM*DIM/4 + 255)/256, 256>>>((const float4*)Wk, wk, DIM*DIM/4);
    cvt_half_kernel<<<(DIM*DIM/4 + 255)/256, 256>>>((const float4*)Wv, wv, DIM*DIM/4);
    cvt_half_kernel<<<(DIM*DIM/4 + 255)/256, 256>>>((const float4*)Wo, wo, DIM*DIM/4);
    cvt_half_kernel<<<(2*HID*DIM/4 + 255)/256, 256>>>((const float4*)W_inv, winv, 2*HID*DIM/4);
    cvt_half_kernel<<<(DIM*HID/4 + 255)/256, 256>>>((const float4*)W_pt, wpt, DIM*HID/4);

    dim3 gq(DIM/BN, MM/BM);          // (9, 64)

    // 1) x = rms(hidden)*(1+scale_msa)+shift_msa  -> half
    modrms_kernel<<<MM, 288>>>(hidden, temb, sst, xh, 0);

    // 2) q,k,v projections
    gemm_f16<0,float><<<gq, 256, GEMM_SMEM>>>(xh, wq, bq, q, DIM, DIM, nullptr, nullptr, nullptr, 0);
    gemm_f16<0,float><<<gq, 256, GEMM_SMEM>>>(xh, wk, bk, k, DIM, DIM, nullptr, nullptr, nullptr, 0);
    gemm_f16<1,float><<<gq, 256, GEMM_SMEM>>>(xh, wv, bv, v, DIM, DIM, nullptr, nullptr, nullptr, 0);

    // 3) kv accumulation + deterministic reduce
    kv_kernel<<<dim3(32, 8), 264>>>(k, v);
    kv_reduce_kernel<<<(BB*HEADS*HD*HDE + 255)/256, 256>>>();

    // 4) out = q.kv, numerator/denominator -> half
    attn_apply_kernel<<<dim3(32, NN/64), dim3(80, 4)>>>(q, attnh);

    // 5) h2 = gate_msa*(attn@Wo^T + bo) + hidden -> f32
    gemm_f16<2,float><<<gq, 256, GEMM_SMEM>>>(attnh, wo, bo, h2, DIM, DIM, hidden, temb, sst, 2);

    // 6) x = rms(h2)*(1+scale_mlp)+shift_mlp -> half
    modrms_kernel<<<MM, 288>>>(h2, temb, sst, xh, 3);

    // 7) y = silu(x@W_inv^T + b_inv) -> half
    gemm_f16<3,__half><<<dim3(HID2/BN, MM/BM), 256, GEMM_SMEM>>>(xh, winv, b_inv, yh, DIM, HID2,
                                                                 nullptr, nullptr, nullptr, 0);

    // 8) depthwise conv + GLU -> half z
    dwglu_kernel<<<(BB*NN*HID + 255)/256, 256>>>(yh, W_dw, b_dw, zh);

    // 9) out = h2 + gate_mlp*(z@W_pt^T) -> f32
    gemm_f16<4,float><<<gq, 256, GEMM_SMEM>>>(zh, wpt, nullptr, out, HID, DIM, h2, temb, sst, 5);
}